// round 2
// baseline (speedup 1.0000x reference)
#include <cuda_runtime.h>
#include <cuda_bf16.h>

// Problem constants
#define BB   32
#define RR   2048
#define CIN  64
#define COUT 64
#define KK   16
#define RBLK (RR / 4)   // 512 r-blocks per k

// Scratch (device globals; no runtime allocation)
__device__ float d_priors[(size_t)KK * BB * RR * COUT];       // 268 MB [K][B][R][COUT]
__device__ float d_partial[(size_t)KK * RBLK * BB * COUT];    // 67 MB  [K][rb][B][COUT]
__device__ float d_logits[KK * BB * RR];                      // 4 MB
__device__ float d_outA[KK * BB * COUT];
__device__ float d_outB[KK * BB * COUT];

// ---- packed f32x2 helpers --------------------------------------------------
__device__ __forceinline__ unsigned long long pk(float lo, float hi) {
    unsigned long long r;
    asm("mov.b64 %0, {%1, %2};" : "=l"(r) : "f"(lo), "f"(hi));
    return r;
}
__device__ __forceinline__ float2 upk(unsigned long long v) {
    float2 f;
    asm("mov.b64 {%0, %1}, %2;" : "=f"(f.x), "=f"(f.y) : "l"(v));
    return f;
}
__device__ __forceinline__ void fma2(unsigned long long& d, unsigned long long a,
                                     unsigned long long b) {
    asm("fma.rn.f32x2 %0, %1, %2, %0;" : "+l"(d) : "l"(a), "l"(b));
}

// ---- GEMM: priors[k][b][r][o] = sum_c x[b][r][c] * W[k][r][c][o] -----------
// Block = (k, 4 consecutive r). 256 threads = 4 groups of 64 (one group per r).
// Thread computes a 4b x 8o tile as 16 f32x2 accumulators (FFMA2, rt=1).
// Epilogue: block-level partial sum over its 4 r's -> d_partial (iter-0 fusion).
// Smem: W tiles 4*16KB + x tiles (transposed [c][b], pad 34) 4*8.5KB = 100352 B.
__global__ void __launch_bounds__(256, 2)
gemm_kernel(const float* __restrict__ x, const float* __restrict__ W) {
    extern __shared__ float sm[];
    float* Ws = sm;                 // 4 * 4096 floats
    float* Xs = sm + 4 * 4096;      // 4 * (64*34) floats

    const int k   = blockIdx.y;
    const int tid = threadIdx.x;
    const int g   = tid >> 6;       // which r within the block
    const int t   = tid & 63;
    const int rb  = blockIdx.x;
    const int r   = (rb << 2) + g;

    // Load W[k][r] (64x64) -> smem, coalesced float4
    {
        const float4* Wg = (const float4*)(W + (((size_t)k * RR + r) << 12));
        float4* Wd = (float4*)(Ws + (g << 12));
#pragma unroll
        for (int i = 0; i < 16; i++) Wd[(i << 6) + t] = Wg[(i << 6) + t];
    }
    // Load x[:, r, :] transposed to [c][b] with pad 34 (float2-aligned, conflict-free)
    {
        float* Xd = Xs + g * 2176;
        const float* Xg = x + ((size_t)r << 6) + t;   // x[b][r][t], b-stride = R*CIN
#pragma unroll
        for (int bb = 0; bb < 32; bb++) Xd[t * 34 + bb] = Xg[(size_t)bb * (RR * CIN)];
    }
    __syncthreads();

    const int b0 = (t & 7) << 2;    // 4 consecutive b
    const int o0 = (t >> 3) << 3;   // 8 consecutive o
    const float* Wr = Ws + (g << 12) + o0;
    const float* Xr = Xs + g * 2176 + b0;

    unsigned long long acc[4][4];
#pragma unroll
    for (int i = 0; i < 4; i++)
#pragma unroll
        for (int j = 0; j < 4; j++) acc[i][j] = 0ULL;

#pragma unroll 8
    for (int c = 0; c < 64; c++) {
        float2 xa = *(const float2*)(Xr + c * 34);
        float2 xb = *(const float2*)(Xr + c * 34 + 2);
        float4 wA = *(const float4*)(Wr + (c << 6));
        float4 wB = *(const float4*)(Wr + (c << 6) + 4);
        unsigned long long w0 = pk(wA.x, wA.y), w1 = pk(wA.z, wA.w);
        unsigned long long w2 = pk(wB.x, wB.y), w3 = pk(wB.z, wB.w);
        unsigned long long xd[4] = {pk(xa.x, xa.x), pk(xa.y, xa.y),
                                    pk(xb.x, xb.x), pk(xb.y, xb.y)};
#pragma unroll
        for (int i = 0; i < 4; i++) {
            fma2(acc[i][0], xd[i], w0);
            fma2(acc[i][1], xd[i], w1);
            fma2(acc[i][2], xd[i], w2);
            fma2(acc[i][3], xd[i], w3);
        }
    }

    // Store priors (global; no smem dependence)
    float vals[4][8];
#pragma unroll
    for (int i = 0; i < 4; i++) {
        float2 a0 = upk(acc[i][0]), a1 = upk(acc[i][1]);
        float2 a2 = upk(acc[i][2]), a3 = upk(acc[i][3]);
        vals[i][0] = a0.x; vals[i][1] = a0.y; vals[i][2] = a1.x; vals[i][3] = a1.y;
        vals[i][4] = a2.x; vals[i][5] = a2.y; vals[i][6] = a3.x; vals[i][7] = a3.y;
        float* dst = d_priors + ((((size_t)k * BB + (b0 + i)) * RR + r) << 6) + o0;
        *(float4*)dst       = make_float4(vals[i][0], vals[i][1], vals[i][2], vals[i][3]);
        *(float4*)(dst + 4) = make_float4(vals[i][4], vals[i][5], vals[i][6], vals[i][7]);
    }

    // ---- fused iter-0 partial: sum this block's 4 r's, deterministic order ----
    __syncthreads();                       // all Ws/Xs reads complete
    float* Ps = sm;                        // reuse smem: [g][b][o] = 4*2048 floats
#pragma unroll
    for (int i = 0; i < 4; i++)
#pragma unroll
        for (int j = 0; j < 8; j++)
            Ps[(g << 11) + ((b0 + i) << 6) + o0 + j] = vals[i][j];
    __syncthreads();

    {
        const int idx = tid << 3;          // 8 consecutive (b,o) slots per thread
        float* dst = d_partial + (((size_t)k * RBLK + rb) << 11) + idx;
        float4 s0, s1;
        const float* p0 = Ps + idx;
        s0 = *(const float4*)(p0);          s1 = *(const float4*)(p0 + 4);
#pragma unroll
        for (int gg = 1; gg < 4; gg++) {
            const float4 q0 = *(const float4*)(p0 + (gg << 11));
            const float4 q1 = *(const float4*)(p0 + (gg << 11) + 4);
            s0.x += q0.x; s0.y += q0.y; s0.z += q0.z; s0.w += q0.w;
            s1.x += q1.x; s1.y += q1.y; s1.z += q1.z; s1.w += q1.w;
        }
        *(float4*)dst       = s0;
        *(float4*)(dst + 4) = s1;
    }
}

// ---- iter-0 finish: outA[k][b] = squash(mean over r) from partials ---------
// Block per (k,b), 256 threads: tid = c*64 + o, chunk c sums rb = c..511 step 4.
__global__ void __launch_bounds__(256)
sum_kernel() {
    const int kb  = blockIdx.x;            // k*32 + b
    const int k   = kb >> 5;
    const int b   = kb & 31;
    const int tid = threadIdx.x;
    const int c   = tid >> 6;
    const int o   = tid & 63;

    __shared__ float sS[4][64];
    __shared__ float sV[64];
    __shared__ float sScale;

    const float* P = d_partial + ((size_t)k * RBLK << 11) + (b << 6) + o;
    float s = 0.f;
#pragma unroll 4
    for (int rb = c; rb < RBLK; rb += 4)
        s += P[(size_t)rb << 11];
    sS[c][o] = s;
    __syncthreads();

    if (tid < 64) {
        float v = (sS[0][tid] + sS[1][tid] + sS[2][tid] + sS[3][tid]) * (1.0f / RR);
        sV[tid] = v;
    }
    __syncthreads();

    if (tid < 32) {
        float a = sV[tid], bb = sV[tid + 32];
        float sq = a * a + bb * bb;
#pragma unroll
        for (int m = 16; m; m >>= 1) sq += __shfl_xor_sync(0xffffffffu, sq, m);
        if (tid == 0) sScale = sqrtf(sq) / (1.f + sq);   // (sq/(1+sq))/sqrt(sq)
    }
    __syncthreads();

    if (tid < 64) d_outA[kb * 64 + tid] = sV[tid] * sScale;
}

// ---- Routing passes 1 & 2 --------------------------------------------------
// PHASE 1: l_r = dot(prior_r, outA); store logits; outB = squash(softmax-sum)
// PHASE 2: l_r = logits_r + dot(prior_r, outB); final -> d_out
// Block per (k,b), 8 warps; warp handles r strided by 8 (unroll 2);
// lane l owns outputs o = 2l, 2l+1 (float2). No max-subtraction needed:
// |logit| <= ||prior||*||out|| with ||out||<1, bounded ~3 -> exp safe in fp32.
template <int PHASE>
__global__ void __launch_bounds__(256)
route_kernel(float* __restrict__ outFinal) {
    const int kb  = blockIdx.x;            // k*32 + b
    const int tid = threadIdx.x;
    const int w   = tid >> 5;
    const int l   = tid & 31;

    __shared__ float sOut[64];
    __shared__ float sS[8][64];
    __shared__ float sZ[8];
    __shared__ float sV[64];
    __shared__ float sScale;

    if (tid < 64)
        sOut[tid] = (PHASE == 1 ? d_outA : d_outB)[kb * 64 + tid];
    __syncthreads();

    float2 o2 = *(float2*)&sOut[l * 2];

    const float2* P = (const float2*)d_priors + (size_t)kb * (RR * 32);
    const float* L = d_logits + kb * RR;

    float sx = 0.f, sy = 0.f, Z = 0.f;
    for (int r = w; r < RR; r += 16) {
        float2 p0 = P[r * 32 + l];
        float2 p1 = P[(r + 8) * 32 + l];
        float dv0 = p0.x * o2.x + p0.y * o2.y;
        float dv1 = p1.x * o2.x + p1.y * o2.y;
#pragma unroll
        for (int m = 16; m; m >>= 1) {
            dv0 += __shfl_xor_sync(0xffffffffu, dv0, m);
            dv1 += __shfl_xor_sync(0xffffffffu, dv1, m);
        }
        float w0, w1;
        if (PHASE == 1) {
            if (l == 0) {
                d_logits[kb * RR + r]     = dv0;
                d_logits[kb * RR + r + 8] = dv1;
            }
            w0 = __expf(dv0);
            w1 = __expf(dv1);
        } else {
            w0 = __expf(L[r] + dv0);
            w1 = __expf(L[r + 8] + dv1);
        }
        sx += w0 * p0.x + w1 * p1.x;
        sy += w0 * p0.y + w1 * p1.y;
        Z  += w0 + w1;
    }

    sS[w][2 * l]     = sx;
    sS[w][2 * l + 1] = sy;
    if (l == 0) sZ[w] = Z;
    __syncthreads();

    if (tid < 64) {
        float v = 0.f;
#pragma unroll
        for (int j = 0; j < 8; j++) v += sS[j][tid];
        float Zt = 0.f;
#pragma unroll
        for (int j = 0; j < 8; j++) Zt += sZ[j];
        sV[tid] = v / Zt;
    }
    __syncthreads();

    if (tid < 32) {
        float a = sV[tid], b = sV[tid + 32];
        float sq = a * a + b * b;
#pragma unroll
        for (int m = 16; m; m >>= 1) sq += __shfl_xor_sync(0xffffffffu, sq, m);
        if (tid == 0) sScale = sqrtf(sq) / (1.f + sq);
    }
    __syncthreads();

    if (tid < 64) {
        float* dst = (PHASE == 1) ? d_outB : outFinal;
        dst[kb * 64 + tid] = sV[tid] * sScale;
    }
}

extern "C" void kernel_launch(void* const* d_in, const int* in_sizes, int n_in,
                              void* d_out, int out_size) {
    const float* x = (const float*)d_in[0];
    const float* W = (const float*)d_in[1];
    if (in_sizes[0] > in_sizes[1]) {  // defensive: x is the smaller tensor
        const float* t = x; x = W; W = t;
    }

    // Dynamic smem > 48KB needs opt-in (host-side attribute set, capture-safe)
    cudaFuncSetAttribute(gemm_kernel, cudaFuncAttributeMaxDynamicSharedMemorySize, 100352);

    gemm_kernel<<<dim3(RBLK, KK, 1), 256, 100352>>>(x, W);
    sum_kernel<<<KK * BB, 256>>>();
    route_kernel<1><<<KK * BB, 256>>>(nullptr);
    route_kernel<2><<<KK * BB, 256>>>((float*)d_out);
}